// round 3
// baseline (speedup 1.0000x reference)
#include <cuda_runtime.h>
#include <cuda_bf16.h>
#include <cstddef>

// Problem constants
#define B_SZ    16
#define S_SZ    16
#define H_SZ    16
#define HD      64
#define D_MODEL 1024
#define PAST    4096
#define L_TOT   4112
#define M_ROWS  256
#define NSPLIT  4

// Output layout offsets (floats): y | k | v
#define OUT_Y_OFF 0
#define OUT_K_OFF (256*1024)
#define OUT_V_OFF (OUT_K_OFF + 256*4112*64)

typedef unsigned long long ull;

// packed fp32x2 helpers (Blackwell FFMA2 pipe — only reachable via PTX)
#define FFMA2(acc, a, b) \
    asm("fma.rn.f32x2 %0, %1, %2, %0;" : "+l"(acc) : "l"(a), "l"(b))
#define MUL2(d, a, b) \
    asm("mul.rn.f32x2 %0, %1, %2;" : "=l"(d) : "l"(a), "l"(b))

__device__ __forceinline__ ull pack2(float x, float y) {
    ull r; asm("mov.b64 %0, {%1, %2};" : "=l"(r) : "f"(x), "f"(y)); return r;
}
__device__ __forceinline__ float2 unpack2(ull v) {
    float2 r; asm("mov.b64 {%0, %1}, %2;" : "=f"(r.x), "=f"(r.y) : "l"(v)); return r;
}

// Scratch (device globals; no allocations allowed)
__device__ float g_qkv [M_ROWS * 3 * D_MODEL];     // [256, 3072]
__device__ float g_obuf[M_ROWS * D_MODEL];         // [256, 1024]
__device__ float g_po  [256 * NSPLIT * 16 * 64];
__device__ float g_pm  [256 * NSPLIT * 16];
__device__ float g_pl  [256 * NSPLIT * 16];

// ---------------------------------------------------------------------------
// Wide GEMM (FFMA2): C[M,N] = A[M,K] @ W[N,K]^T + bias. Tile 64m x 128n.
// 256 threads, 4m x 8n per thread. Used for QKV projection (96 blocks).
// ---------------------------------------------------------------------------
__global__ __launch_bounds__(256)
void gemm_bias_wide_kernel(const float* __restrict__ A, const float* __restrict__ W,
                           const float* __restrict__ bias, float* __restrict__ C,
                           int N, int K) {
    __shared__ float As[16][68];
    __shared__ float Bs[16][132];

    const int tid = threadIdx.x;
    const int tx = tid & 15;          // n group (8 cols)
    const int ty = tid >> 4;          // m group (4 rows)
    const int m0 = blockIdx.y * 64;
    const int n0 = blockIdx.x * 128;

    const int lrA = tid >> 2;         // 0..63
    const int lkA = (tid & 3) * 4;
    const int lrB = tid >> 1;         // 0..127
    const int lkB = (tid & 1) * 8;

    ull c2[4][4];
    #pragma unroll
    for (int i = 0; i < 4; i++)
        #pragma unroll
        for (int j = 0; j < 4; j++) c2[i][j] = 0ull;

    for (int k0 = 0; k0 < K; k0 += 16) {
        float4 a4 = *(const float4*)&A[(size_t)(m0 + lrA) * K + k0 + lkA];
        As[lkA + 0][lrA] = a4.x; As[lkA + 1][lrA] = a4.y;
        As[lkA + 2][lrA] = a4.z; As[lkA + 3][lrA] = a4.w;
        float4 b4a = *(const float4*)&W[(size_t)(n0 + lrB) * K + k0 + lkB];
        float4 b4b = *(const float4*)&W[(size_t)(n0 + lrB) * K + k0 + lkB + 4];
        Bs[lkB + 0][lrB] = b4a.x; Bs[lkB + 1][lrB] = b4a.y;
        Bs[lkB + 2][lrB] = b4a.z; Bs[lkB + 3][lrB] = b4a.w;
        Bs[lkB + 4][lrB] = b4b.x; Bs[lkB + 5][lrB] = b4b.y;
        Bs[lkB + 6][lrB] = b4b.z; Bs[lkB + 7][lrB] = b4b.w;
        __syncthreads();

        #pragma unroll
        for (int kk = 0; kk < 16; kk++) {
            float4 av = *(const float4*)&As[kk][ty * 4];
            ulonglong2 b01 = *(const ulonglong2*)&Bs[kk][tx * 8];
            ulonglong2 b23 = *(const ulonglong2*)&Bs[kk][tx * 8 + 4];
            ull pa0 = pack2(av.x, av.x), pa1 = pack2(av.y, av.y);
            ull pa2 = pack2(av.z, av.z), pa3 = pack2(av.w, av.w);
            FFMA2(c2[0][0], pa0, b01.x); FFMA2(c2[0][1], pa0, b01.y);
            FFMA2(c2[0][2], pa0, b23.x); FFMA2(c2[0][3], pa0, b23.y);
            FFMA2(c2[1][0], pa1, b01.x); FFMA2(c2[1][1], pa1, b01.y);
            FFMA2(c2[1][2], pa1, b23.x); FFMA2(c2[1][3], pa1, b23.y);
            FFMA2(c2[2][0], pa2, b01.x); FFMA2(c2[2][1], pa2, b01.y);
            FFMA2(c2[2][2], pa2, b23.x); FFMA2(c2[2][3], pa2, b23.y);
            FFMA2(c2[3][0], pa3, b01.x); FFMA2(c2[3][1], pa3, b01.y);
            FFMA2(c2[3][2], pa3, b23.x); FFMA2(c2[3][3], pa3, b23.y);
        }
        __syncthreads();
    }

    float4 bb0 = *(const float4*)&bias[n0 + tx * 8];
    float4 bb1 = *(const float4*)&bias[n0 + tx * 8 + 4];
    #pragma unroll
    for (int i = 0; i < 4; i++) {
        float2 p0 = unpack2(c2[i][0]), p1 = unpack2(c2[i][1]);
        float2 p2 = unpack2(c2[i][2]), p3 = unpack2(c2[i][3]);
        float4 r0 = make_float4(p0.x + bb0.x, p0.y + bb0.y, p1.x + bb0.z, p1.y + bb0.w);
        float4 r1 = make_float4(p2.x + bb1.x, p2.y + bb1.y, p3.x + bb1.z, p3.y + bb1.w);
        float* dst = &C[(size_t)(m0 + ty * 4 + i) * N + n0 + tx * 8];
        *(float4*)dst = r0;
        *(float4*)(dst + 4) = r1;
    }
}

// ---------------------------------------------------------------------------
// Narrow GEMM (kept for out-projection: more blocks at N=1024)
// ---------------------------------------------------------------------------
__global__ __launch_bounds__(256)
void gemm_bias_kernel(const float* __restrict__ A, const float* __restrict__ W,
                      const float* __restrict__ bias, float* __restrict__ C,
                      int N, int K) {
    __shared__ float As[16][68];
    __shared__ float Bs[16][68];

    const int tid = threadIdx.x;
    const int tx = tid & 15;
    const int ty = tid >> 4;
    const int m0 = blockIdx.y * 64;
    const int n0 = blockIdx.x * 64;
    const int lr = tid >> 2;
    const int lk = (tid & 3) * 4;

    ull c2[4][2];
    #pragma unroll
    for (int i = 0; i < 4; i++) { c2[i][0] = 0ull; c2[i][1] = 0ull; }

    for (int k0 = 0; k0 < K; k0 += 16) {
        float4 a4 = *(const float4*)&A[(size_t)(m0 + lr) * K + k0 + lk];
        float4 b4 = *(const float4*)&W[(size_t)(n0 + lr) * K + k0 + lk];
        As[lk + 0][lr] = a4.x; As[lk + 1][lr] = a4.y;
        As[lk + 2][lr] = a4.z; As[lk + 3][lr] = a4.w;
        Bs[lk + 0][lr] = b4.x; Bs[lk + 1][lr] = b4.y;
        Bs[lk + 2][lr] = b4.z; Bs[lk + 3][lr] = b4.w;
        __syncthreads();

        #pragma unroll
        for (int kk = 0; kk < 16; kk++) {
            float4 av = *(const float4*)&As[kk][ty * 4];
            ulonglong2 bv = *(const ulonglong2*)&Bs[kk][tx * 4];
            ull pa0 = pack2(av.x, av.x), pa1 = pack2(av.y, av.y);
            ull pa2 = pack2(av.z, av.z), pa3 = pack2(av.w, av.w);
            FFMA2(c2[0][0], pa0, bv.x); FFMA2(c2[0][1], pa0, bv.y);
            FFMA2(c2[1][0], pa1, bv.x); FFMA2(c2[1][1], pa1, bv.y);
            FFMA2(c2[2][0], pa2, bv.x); FFMA2(c2[2][1], pa2, bv.y);
            FFMA2(c2[3][0], pa3, bv.x); FFMA2(c2[3][1], pa3, bv.y);
        }
        __syncthreads();
    }

    float4 bb = *(const float4*)&bias[n0 + tx * 4];
    #pragma unroll
    for (int i = 0; i < 4; i++) {
        float2 p0 = unpack2(c2[i][0]), p1 = unpack2(c2[i][1]);
        float4 r = make_float4(p0.x + bb.x, p0.y + bb.y, p1.x + bb.z, p1.y + bb.w);
        *(float4*)&C[(size_t)(m0 + ty * 4 + i) * N + n0 + tx * 4] = r;
    }
}

// ---------------------------------------------------------------------------
// Scatter freshly projected K/V rows into positions [4096, 4112).
// ---------------------------------------------------------------------------
__global__ __launch_bounds__(256)
void scatter_newkv_kernel(float* __restrict__ Kd, float* __restrict__ Vd) {
    const unsigned i = blockIdx.x * 256u + threadIdx.x;    // < 65536
    const unsigned c = i & 15u;
    const unsigned s = (i >> 4) & 15u;
    const unsigned h = (i >> 8) & 15u;
    const unsigned b = i >> 12;
    const size_t qoff = (size_t)(b * 16 + s) * 3072 + h * 64 + c * 4;
    const size_t doff = ((size_t)(b * 16 + h) * L_TOT + PAST + s) * 64 + c * 4;
    *(float4*)&Kd[doff] = *(const float4*)&g_qkv[qoff + 1024];
    *(float4*)&Vd[doff] = *(const float4*)&g_qkv[qoff + 2048];
}

// ---------------------------------------------------------------------------
// Fused attention + cache copy-out, split-KV, FFMA2 math.
// ---------------------------------------------------------------------------
__global__ __launch_bounds__(256)
void attn_split_kernel(const float* __restrict__ cache_k,
                       const float* __restrict__ cache_v,
                       float* __restrict__ out_k,
                       float* __restrict__ out_v) {
    __shared__ float qs [16][68];
    __shared__ float kt [64][68];     // also reused as epilogue exchange buffer
    __shared__ float vt [64][64];
    __shared__ float ptT[16][68];
    __shared__ float m_run[16], l_run[16], fac_s[16];

    const int tid   = threadIdx.x;
    const int bh    = blockIdx.x >> 2;
    const int split = blockIdx.x & 3;
    const int b = bh >> 4, h = bh & 15;

    // Load q (pre-scaled by 1/sqrt(64))
    {
        const int q = tid >> 4, c4 = tid & 15;
        float4 qv = *(const float4*)&g_qkv[(size_t)(b * 16 + q) * 3072 + h * 64 + c4 * 4];
        qs[q][c4 * 4 + 0] = qv.x * 0.125f;
        qs[q][c4 * 4 + 1] = qv.y * 0.125f;
        qs[q][c4 * 4 + 2] = qv.z * 0.125f;
        qs[q][c4 * 4 + 3] = qv.w * 0.125f;
    }
    if (tid < 16) { m_run[tid] = -1e30f; l_run[tid] = 0.0f; }

    const int chunk0 = split * 1024;
    const int nrows  = (split == 3) ? 1040 : 1024;
    const size_t cbase = (size_t)bh * (PAST * 64);
    const size_t obase = (size_t)bh * (L_TOT * 64);

    const int qg = tid >> 6;           // score: query group
    const int kp = tid & 63;           // score: k row
    const int pq = tid >> 4;           // softmax/AV: query
    const int dc = tid & 15;           // softmax: segment
    const int dc8   = dc & 7;          // AV: 8-dim group
    const int rhalf = dc >> 3;         // AV: row half
    const int rbase = rhalf * 32;

    ull o0 = 0ull, o1 = 0ull, o2 = 0ull, o3 = 0ull;   // 8 output dims (4 f32x2)

    const int ntiles = (split == 3) ? 17 : 16;
    for (int t = 0; t < ntiles; t++) {
        const int l0   = chunk0 + t * 64;
        const int rows = min(64, chunk0 + nrows - l0);   // 64 or 16
        __syncthreads();

        // ---- stage K/V tile (fused copy-out for cache rows) ----
        #pragma unroll
        for (int i = 0; i < 4; i++) {
            int idx = i * 256 + tid;
            int r = idx >> 4, c = idx & 15;
            if (r < rows) {
                int gl = l0 + r;
                float4 k4, v4;
                if (gl < PAST) {
                    k4 = *(const float4*)&cache_k[cbase + (size_t)gl * 64 + c * 4];
                    v4 = *(const float4*)&cache_v[cbase + (size_t)gl * 64 + c * 4];
                    *(float4*)&out_k[obase + (size_t)gl * 64 + c * 4] = k4;
                    *(float4*)&out_v[obase + (size_t)gl * 64 + c * 4] = v4;
                } else {
                    k4 = *(const float4*)&out_k[obase + (size_t)gl * 64 + c * 4];
                    v4 = *(const float4*)&out_v[obase + (size_t)gl * 64 + c * 4];
                }
                *(float4*)&kt[r][c * 4] = k4;
                *(float4*)&vt[r][c * 4] = v4;
            }
        }
        __syncthreads();

        // ---- scores (FFMA2 pairs along head-dim) ----
        {
            ull a0 = 0ull, a1 = 0ull, a2 = 0ull, a3 = 0ull;
            #pragma unroll
            for (int c = 0; c < 16; c++) {
                ulonglong2 k2 = *(const ulonglong2*)&kt[kp][c * 4];
                ulonglong2 q0 = *(const ulonglong2*)&qs[qg * 4 + 0][c * 4];
                ulonglong2 q1 = *(const ulonglong2*)&qs[qg * 4 + 1][c * 4];
                ulonglong2 q2 = *(const ulonglong2*)&qs[qg * 4 + 2][c * 4];
                ulonglong2 q3 = *(const ulonglong2*)&qs[qg * 4 + 3][c * 4];
                FFMA2(a0, k2.x, q0.x); FFMA2(a0, k2.y, q0.y);
                FFMA2(a1, k2.x, q1.x); FFMA2(a1, k2.y, q1.y);
                FFMA2(a2, k2.x, q2.x); FFMA2(a2, k2.y, q2.y);
                FFMA2(a3, k2.x, q3.x); FFMA2(a3, k2.y, q3.y);
            }
            float2 f0 = unpack2(a0), f1 = unpack2(a1);
            float2 f2 = unpack2(a2), f3 = unpack2(a3);
            bool valid = kp < rows;
            ptT[qg * 4 + 0][kp] = valid ? (f0.x + f0.y) : -1e30f;
            ptT[qg * 4 + 1][kp] = valid ? (f1.x + f1.y) : -1e30f;
            ptT[qg * 4 + 2][kp] = valid ? (f2.x + f2.y) : -1e30f;
            ptT[qg * 4 + 3][kp] = valid ? (f3.x + f3.y) : -1e30f;
        }
        __syncthreads();

        // ---- softmax partial (per query, 16-lane groups) ----
        {
            float4 p = *(const float4*)&ptT[pq][dc * 4];
            float mt = fmaxf(fmaxf(p.x, p.y), fmaxf(p.z, p.w));
            #pragma unroll
            for (int s = 8; s >= 1; s >>= 1)
                mt = fmaxf(mt, __shfl_xor_sync(0xffffffffu, mt, s, 16));
            float mo = m_run[pq];
            float mn = fmaxf(mo, mt);
            float fc = __expf(mo - mn);
            p.x = __expf(p.x - mn); p.y = __expf(p.y - mn);
            p.z = __expf(p.z - mn); p.w = __expf(p.w - mn);
            *(float4*)&ptT[pq][dc * 4] = p;
            float ss = p.x + p.y + p.z + p.w;
            #pragma unroll
            for (int s = 8; s >= 1; s >>= 1)
                ss += __shfl_xor_sync(0xffffffffu, ss, s, 16);
            if (dc == 0) {
                m_run[pq] = mn;
                fac_s[pq] = fc;
                l_run[pq] = l_run[pq] * fc + ss;
            }
        }
        __syncthreads();

        // ---- AV (FFMA2): thread = (pq, dc8, rhalf); 8 dims x 32 rows ----
        {
            float f = fac_s[pq];
            ull f2 = pack2(f, f);
            MUL2(o0, o0, f2); MUL2(o1, o1, f2);
            MUL2(o2, o2, f2); MUL2(o3, o3, f2);

            #pragma unroll 2
            for (int r0 = 0; r0 < 32; r0 += 4) {
                float4 p4 = *(const float4*)&ptT[pq][rbase + r0];
                {
                    ull pj = pack2(p4.x, p4.x);
                    ulonglong2 va = *(const ulonglong2*)&vt[rbase + r0 + 0][dc8 * 8];
                    ulonglong2 vb = *(const ulonglong2*)&vt[rbase + r0 + 0][dc8 * 8 + 4];
                    FFMA2(o0, pj, va.x); FFMA2(o1, pj, va.y);
                    FFMA2(o2, pj, vb.x); FFMA2(o3, pj, vb.y);
                }
                {
                    ull pj = pack2(p4.y, p4.y);
                    ulonglong2 va = *(const ulonglong2*)&vt[rbase + r0 + 1][dc8 * 8];
                    ulonglong2 vb = *(const ulonglong2*)&vt[rbase + r0 + 1][dc8 * 8 + 4];
                    FFMA2(o0, pj, va.x); FFMA2(o1, pj, va.y);
                    FFMA2(o2, pj, vb.x); FFMA2(o3, pj, vb.y);
                }
                {
                    ull pj = pack2(p4.z, p4.z);
                    ulonglong2 va = *(const ulonglong2*)&vt[rbase + r0 + 2][dc8 * 8];
                    ulonglong2 vb = *(const ulonglong2*)&vt[rbase + r0 + 2][dc8 * 8 + 4];
                    FFMA2(o0, pj, va.x); FFMA2(o1, pj, va.y);
                    FFMA2(o2, pj, vb.x); FFMA2(o3, pj, vb.y);
                }
                {
                    ull pj = pack2(p4.w, p4.w);
                    ulonglong2 va = *(const ulonglong2*)&vt[rbase + r0 + 3][dc8 * 8];
                    ulonglong2 vb = *(const ulonglong2*)&vt[rbase + r0 + 3][dc8 * 8 + 4];
                    FFMA2(o0, pj, va.x); FFMA2(o1, pj, va.y);
                    FFMA2(o2, pj, vb.x); FFMA2(o3, pj, vb.y);
                }
            }
        }
    }

    // ---- epilogue: combine row halves, write partials ----
    __syncthreads();
    float* xch = &kt[0][0];   // reuse kt: 2*16*64 floats = 8 KB
    {
        ulonglong2 w0; w0.x = o0; w0.y = o1;
        ulonglong2 w1; w1.x = o2; w1.y = o3;
        float* dst = &xch[((rhalf * 16) + pq) * 64 + dc8 * 8];
        *(ulonglong2*)dst = w0;
        *(ulonglong2*)(dst + 4) = w1;
    }
    __syncthreads();

    if (rhalf == 0) {
        const float* s0 = &xch[pq * 64 + dc8 * 8];
        const float* s1 = &xch[(16 + pq) * 64 + dc8 * 8];
        float4 r0, r1;
        r0.x = s0[0] + s1[0]; r0.y = s0[1] + s1[1];
        r0.z = s0[2] + s1[2]; r0.w = s0[3] + s1[3];
        r1.x = s0[4] + s1[4]; r1.y = s0[5] + s1[5];
        r1.z = s0[6] + s1[6]; r1.w = s0[7] + s1[7];
        const size_t pbase = (size_t)blockIdx.x * 1024;
        *(float4*)&g_po[pbase + pq * 64 + dc8 * 8] = r0;
        *(float4*)&g_po[pbase + pq * 64 + dc8 * 8 + 4] = r1;
    }
    if (tid < 16) {
        g_pm[blockIdx.x * 16 + tid] = m_run[tid];
        g_pl[blockIdx.x * 16 + tid] = l_run[tid];
    }
}

// ---------------------------------------------------------------------------
// Combine split partials -> g_obuf [B,S,H*hd]
// ---------------------------------------------------------------------------
__global__ __launch_bounds__(256)
void attn_reduce_kernel() {
    const int bh = blockIdx.x;
    const int tid = threadIdx.x;
    const int pq = tid >> 4, dc = tid & 15;
    const int base = bh * NSPLIT;

    float mm = -1e30f;
    #pragma unroll
    for (int s = 0; s < NSPLIT; s++)
        mm = fmaxf(mm, g_pm[(base + s) * 16 + pq]);

    float4 acc = make_float4(0.f, 0.f, 0.f, 0.f);
    float l = 0.f;
    #pragma unroll
    for (int s = 0; s < NSPLIT; s++) {
        float w = __expf(g_pm[(base + s) * 16 + pq] - mm);
        float4 o = *(const float4*)&g_po[(size_t)(base + s) * 1024 + pq * 64 + dc * 4];
        acc.x += w * o.x; acc.y += w * o.y;
        acc.z += w * o.z; acc.w += w * o.w;
        l += w * g_pl[(base + s) * 16 + pq];
    }
    float inv = 1.0f / l;
    const int b = bh >> 4, h = bh & 15;
    float4 r = make_float4(acc.x * inv, acc.y * inv, acc.z * inv, acc.w * inv);
    *(float4*)&g_obuf[(size_t)(b * 16 + pq) * D_MODEL + h * 64 + dc * 4] = r;
}

// ---------------------------------------------------------------------------
extern "C" void kernel_launch(void* const* d_in, const int* in_sizes, int n_in,
                              void* d_out, int out_size) {
    const float* x       = (const float*)d_in[0];
    const float* cache_k = (const float*)d_in[1];
    const float* cache_v = (const float*)d_in[2];
    const float* qkv_w   = (const float*)d_in[3];
    const float* qkv_b   = (const float*)d_in[4];
    const float* out_w   = (const float*)d_in[5];
    const float* out_b   = (const float*)d_in[6];

    float* out   = (float*)d_out;
    float* out_y = out + OUT_Y_OFF;
    float* out_k = out + OUT_K_OFF;
    float* out_v = out + OUT_V_OFF;

    float *qkv_p = nullptr, *obuf_p = nullptr;
    cudaGetSymbolAddress((void**)&qkv_p,  g_qkv);
    cudaGetSymbolAddress((void**)&obuf_p, g_obuf);

    // 1) QKV projection -> g_qkv [256,3072]  (wide FFMA2 GEMM, 96 blocks)
    gemm_bias_wide_kernel<<<dim3(3072 / 128, M_ROWS / 64), 256>>>(
        x, qkv_w, qkv_b, qkv_p, 3072, D_MODEL);

    // 2) Append new K/V rows into out_k/out_v tails
    scatter_newkv_kernel<<<256, 256>>>(out_k, out_v);

    // 3) Fused attention + cache copy-out (split-KV x4, FFMA2)
    attn_split_kernel<<<B_SZ * H_SZ * NSPLIT, 256>>>(cache_k, cache_v, out_k, out_v);

    // 4) Combine splits -> g_obuf
    attn_reduce_kernel<<<B_SZ * H_SZ, 256>>>();

    // 5) Output projection -> y
    gemm_bias_kernel<<<dim3(D_MODEL / 64, M_ROWS / 64), 256>>>(
        obuf_p, out_w, out_b, out_y, D_MODEL, D_MODEL);
}

// round 4
// speedup vs baseline: 1.2023x; 1.2023x over previous
#include <cuda_runtime.h>
#include <cuda_bf16.h>
#include <cstddef>

// Problem constants
#define B_SZ    16
#define S_SZ    16
#define H_SZ    16
#define HD      64
#define D_MODEL 1024
#define PAST    4096
#define L_TOT   4112
#define M_ROWS  256
#define NSPLIT  4

// Output layout offsets (floats): y | k | v
#define OUT_Y_OFF 0
#define OUT_K_OFF (256*1024)
#define OUT_V_OFF (OUT_K_OFF + 256*4112*64)

// Scratch (device globals; no allocations allowed)
__device__ float g_qkv [M_ROWS * 3 * D_MODEL];     // [256, 3072]
__device__ float g_obuf[M_ROWS * D_MODEL];         // [256, 1024]
__device__ float g_po  [256 * NSPLIT * 16 * 64];
__device__ float g_pm  [256 * NSPLIT * 16];
__device__ float g_pl  [256 * NSPLIT * 16];

// ---------------------------------------------------------------------------
// GEMM: C[M,N] = A[M,K] @ W[N,K]^T + bias[N]   (row-major fp32)
// ---------------------------------------------------------------------------
__global__ __launch_bounds__(256)
void gemm_bias_kernel(const float* __restrict__ A, const float* __restrict__ W,
                      const float* __restrict__ bias, float* __restrict__ C,
                      int N, int K) {
    __shared__ float As[16][68];
    __shared__ float Bs[16][68];

    const int tid = threadIdx.x;
    const int tx = tid & 15;
    const int ty = tid >> 4;
    const int m0 = blockIdx.y * 64;
    const int n0 = blockIdx.x * 64;
    const int lr = tid >> 2;
    const int lk = (tid & 3) * 4;

    float c[4][4] = {};

    for (int k0 = 0; k0 < K; k0 += 16) {
        float4 a4 = *(const float4*)&A[(size_t)(m0 + lr) * K + k0 + lk];
        float4 b4 = *(const float4*)&W[(size_t)(n0 + lr) * K + k0 + lk];
        As[lk + 0][lr] = a4.x; As[lk + 1][lr] = a4.y;
        As[lk + 2][lr] = a4.z; As[lk + 3][lr] = a4.w;
        Bs[lk + 0][lr] = b4.x; Bs[lk + 1][lr] = b4.y;
        Bs[lk + 2][lr] = b4.z; Bs[lk + 3][lr] = b4.w;
        __syncthreads();

        #pragma unroll
        for (int kk = 0; kk < 16; kk++) {
            float4 av = *(const float4*)&As[kk][ty * 4];
            float4 bv = *(const float4*)&Bs[kk][tx * 4];
            c[0][0] += av.x * bv.x; c[0][1] += av.x * bv.y;
            c[0][2] += av.x * bv.z; c[0][3] += av.x * bv.w;
            c[1][0] += av.y * bv.x; c[1][1] += av.y * bv.y;
            c[1][2] += av.y * bv.z; c[1][3] += av.y * bv.w;
            c[2][0] += av.z * bv.x; c[2][1] += av.z * bv.y;
            c[2][2] += av.z * bv.z; c[2][3] += av.z * bv.w;
            c[3][0] += av.w * bv.x; c[3][1] += av.w * bv.y;
            c[3][2] += av.w * bv.z; c[3][3] += av.w * bv.w;
        }
        __syncthreads();
    }

    float4 bb = *(const float4*)&bias[n0 + tx * 4];
    #pragma unroll
    for (int i = 0; i < 4; i++) {
        float4 r = make_float4(c[i][0] + bb.x, c[i][1] + bb.y,
                               c[i][2] + bb.z, c[i][3] + bb.w);
        *(float4*)&C[(size_t)(m0 + ty * 4 + i) * N + n0 + tx * 4] = r;
    }
}

// ---------------------------------------------------------------------------
// Scatter freshly projected K/V rows into positions [4096, 4112).
// ---------------------------------------------------------------------------
__global__ __launch_bounds__(256)
void scatter_newkv_kernel(float* __restrict__ Kd, float* __restrict__ Vd) {
    const unsigned i = blockIdx.x * 256u + threadIdx.x;    // < 65536
    const unsigned c = i & 15u;
    const unsigned s = (i >> 4) & 15u;
    const unsigned h = (i >> 8) & 15u;
    const unsigned b = i >> 12;
    const size_t qoff = (size_t)(b * 16 + s) * 3072 + h * 64 + c * 4;
    const size_t doff = ((size_t)(b * 16 + h) * L_TOT + PAST + s) * 64 + c * 4;
    *(float4*)&Kd[doff] = *(const float4*)&g_qkv[qoff + 1024];
    *(float4*)&Vd[doff] = *(const float4*)&g_qkv[qoff + 2048];
}

// ---------------------------------------------------------------------------
// Fused attention + cache copy-out, split-KV.
// AV phase uses 4-query coarsening: thread = (row-quarter, query-quad,
// dim-chunk) -> V chunks read once per row-quarter (16x less re-read),
// p read as float4 broadcasts from ptT[q][r].
// ---------------------------------------------------------------------------
__global__ __launch_bounds__(256)
void attn_split_kernel(const float* __restrict__ cache_k,
                       const float* __restrict__ cache_v,
                       float* __restrict__ out_k,
                       float* __restrict__ out_v) {
    __shared__ float qs [16][68];
    __shared__ float kt [64][68];     // reused as epilogue reduce buffer
    __shared__ float vt [64][64];
    __shared__ float ptT[16][68];
    __shared__ float m_run[16], l_run[16], fac_s[16];

    const int tid   = threadIdx.x;
    const int bh    = blockIdx.x >> 2;
    const int split = blockIdx.x & 3;
    const int b = bh >> 4, h = bh & 15;

    // Load q (pre-scaled by 1/sqrt(64))
    {
        const int q = tid >> 4, c4 = tid & 15;
        float4 qv = *(const float4*)&g_qkv[(size_t)(b * 16 + q) * 3072 + h * 64 + c4 * 4];
        qs[q][c4 * 4 + 0] = qv.x * 0.125f;
        qs[q][c4 * 4 + 1] = qv.y * 0.125f;
        qs[q][c4 * 4 + 2] = qv.z * 0.125f;
        qs[q][c4 * 4 + 3] = qv.w * 0.125f;
    }
    if (tid < 16) { m_run[tid] = -1e30f; l_run[tid] = 0.0f; }

    const int chunk0 = split * 1024;
    const int nrows  = (split == 3) ? 1040 : 1024;
    const size_t cbase = (size_t)bh * (PAST * 64);
    const size_t obase = (size_t)bh * (L_TOT * 64);

    const int qg = tid >> 6;           // score: query group
    const int kp = tid & 63;           // score: k row
    const int pq = tid >> 4;           // softmax: query
    const int dc = tid & 15;           // softmax: segment / epilogue dim

    // AV mapping: 4 queries x 4 dims per thread over a 16-row quarter
    const int rq  = tid >> 6;          // row quarter (16 rows)
    const int qq  = (tid >> 4) & 3;    // query quad
    const int dcA = tid & 15;          // dim chunk

    float4 o0 = make_float4(0.f,0.f,0.f,0.f);
    float4 o1 = make_float4(0.f,0.f,0.f,0.f);
    float4 o2 = make_float4(0.f,0.f,0.f,0.f);
    float4 o3 = make_float4(0.f,0.f,0.f,0.f);

    const int ntiles = (split == 3) ? 17 : 16;
    for (int t = 0; t < ntiles; t++) {
        const int l0   = chunk0 + t * 64;
        const int rows = min(64, chunk0 + nrows - l0);   // 64 or 16
        __syncthreads();   // previous tile fully consumed

        // ---- stage K/V tile (fused copy-out for cache rows) ----
        #pragma unroll
        for (int i = 0; i < 4; i++) {
            int idx = i * 256 + tid;
            int r = idx >> 4, c = idx & 15;
            if (r < rows) {
                int gl = l0 + r;
                float4 k4, v4;
                if (gl < PAST) {
                    k4 = *(const float4*)&cache_k[cbase + (size_t)gl * 64 + c * 4];
                    v4 = *(const float4*)&cache_v[cbase + (size_t)gl * 64 + c * 4];
                    *(float4*)&out_k[obase + (size_t)gl * 64 + c * 4] = k4;
                    *(float4*)&out_v[obase + (size_t)gl * 64 + c * 4] = v4;
                } else {
                    k4 = *(const float4*)&out_k[obase + (size_t)gl * 64 + c * 4];
                    v4 = *(const float4*)&out_v[obase + (size_t)gl * 64 + c * 4];
                }
                *(float4*)&kt[r][c * 4] = k4;
                *(float4*)&vt[r][c * 4] = v4;
            }
        }
        __syncthreads();

        // ---- scores: thread = (4 queries qg*4.., k row kp) ----
        {
            float a0 = 0.f, a1 = 0.f, a2 = 0.f, a3 = 0.f;
            #pragma unroll
            for (int c = 0; c < 16; c++) {
                float4 k4 = *(const float4*)&kt[kp][c * 4];
                float4 q0 = *(const float4*)&qs[qg * 4 + 0][c * 4];
                float4 q1 = *(const float4*)&qs[qg * 4 + 1][c * 4];
                float4 q2 = *(const float4*)&qs[qg * 4 + 2][c * 4];
                float4 q3 = *(const float4*)&qs[qg * 4 + 3][c * 4];
                a0 += k4.x*q0.x + k4.y*q0.y + k4.z*q0.z + k4.w*q0.w;
                a1 += k4.x*q1.x + k4.y*q1.y + k4.z*q1.z + k4.w*q1.w;
                a2 += k4.x*q2.x + k4.y*q2.y + k4.z*q2.z + k4.w*q2.w;
                a3 += k4.x*q3.x + k4.y*q3.y + k4.z*q3.z + k4.w*q3.w;
            }
            bool valid = kp < rows;
            ptT[qg * 4 + 0][kp] = valid ? a0 : -1e30f;
            ptT[qg * 4 + 1][kp] = valid ? a1 : -1e30f;
            ptT[qg * 4 + 2][kp] = valid ? a2 : -1e30f;
            ptT[qg * 4 + 3][kp] = valid ? a3 : -1e30f;
        }
        __syncthreads();

        // ---- softmax partial: thread = (q=pq, seg=dc) over 4 scores ----
        {
            float4 p = *(const float4*)&ptT[pq][dc * 4];
            float mt = fmaxf(fmaxf(p.x, p.y), fmaxf(p.z, p.w));
            #pragma unroll
            for (int s = 8; s >= 1; s >>= 1)
                mt = fmaxf(mt, __shfl_xor_sync(0xffffffffu, mt, s, 16));
            float mo = m_run[pq];
            float mn = fmaxf(mo, mt);
            float fc = __expf(mo - mn);
            p.x = __expf(p.x - mn); p.y = __expf(p.y - mn);
            p.z = __expf(p.z - mn); p.w = __expf(p.w - mn);
            *(float4*)&ptT[pq][dc * 4] = p;
            float ss = p.x + p.y + p.z + p.w;
            #pragma unroll
            for (int s = 8; s >= 1; s >>= 1)
                ss += __shfl_xor_sync(0xffffffffu, ss, s, 16);
            if (dc == 0) {
                m_run[pq] = mn;
                fac_s[pq] = fc;
                l_run[pq] = l_run[pq] * fc + ss;
            }
        }
        __syncthreads();

        // ---- AV: thread = (rq, qq, dcA): 4 q x 4 dims over 16 rows ----
        {
            o0.x *= fac_s[qq*4+0]; o0.y *= fac_s[qq*4+0];
            o0.z *= fac_s[qq*4+0]; o0.w *= fac_s[qq*4+0];
            o1.x *= fac_s[qq*4+1]; o1.y *= fac_s[qq*4+1];
            o1.z *= fac_s[qq*4+1]; o1.w *= fac_s[qq*4+1];
            o2.x *= fac_s[qq*4+2]; o2.y *= fac_s[qq*4+2];
            o2.z *= fac_s[qq*4+2]; o2.w *= fac_s[qq*4+2];
            o3.x *= fac_s[qq*4+3]; o3.y *= fac_s[qq*4+3];
            o3.z *= fac_s[qq*4+3]; o3.w *= fac_s[qq*4+3];

            const int rbase = rq * 16;
            #pragma unroll
            for (int rg = 0; rg < 4; rg++) {
                const int r0 = rbase + rg * 4;
                float4 v0 = *(const float4*)&vt[r0 + 0][dcA * 4];
                float4 v1 = *(const float4*)&vt[r0 + 1][dcA * 4];
                float4 v2 = *(const float4*)&vt[r0 + 2][dcA * 4];
                float4 v3 = *(const float4*)&vt[r0 + 3][dcA * 4];
                {
                    float4 p4 = *(const float4*)&ptT[qq*4+0][r0];
                    o0.x += p4.x*v0.x + p4.y*v1.x + p4.z*v2.x + p4.w*v3.x;
                    o0.y += p4.x*v0.y + p4.y*v1.y + p4.z*v2.y + p4.w*v3.y;
                    o0.z += p4.x*v0.z + p4.y*v1.z + p4.z*v2.z + p4.w*v3.z;
                    o0.w += p4.x*v0.w + p4.y*v1.w + p4.z*v2.w + p4.w*v3.w;
                }
                {
                    float4 p4 = *(const float4*)&ptT[qq*4+1][r0];
                    o1.x += p4.x*v0.x + p4.y*v1.x + p4.z*v2.x + p4.w*v3.x;
                    o1.y += p4.x*v0.y + p4.y*v1.y + p4.z*v2.y + p4.w*v3.y;
                    o1.z += p4.x*v0.z + p4.y*v1.z + p4.z*v2.z + p4.w*v3.z;
                    o1.w += p4.x*v0.w + p4.y*v1.w + p4.z*v2.w + p4.w*v3.w;
                }
                {
                    float4 p4 = *(const float4*)&ptT[qq*4+2][r0];
                    o2.x += p4.x*v0.x + p4.y*v1.x + p4.z*v2.x + p4.w*v3.x;
                    o2.y += p4.x*v0.y + p4.y*v1.y + p4.z*v2.y + p4.w*v3.y;
                    o2.z += p4.x*v0.z + p4.y*v1.z + p4.z*v2.z + p4.w*v3.z;
                    o2.w += p4.x*v0.w + p4.y*v1.w + p4.z*v2.w + p4.w*v3.w;
                }
                {
                    float4 p4 = *(const float4*)&ptT[qq*4+3][r0];
                    o3.x += p4.x*v0.x + p4.y*v1.x + p4.z*v2.x + p4.w*v3.x;
                    o3.y += p4.x*v0.y + p4.y*v1.y + p4.z*v2.y + p4.w*v3.y;
                    o3.z += p4.x*v0.z + p4.y*v1.z + p4.z*v2.z + p4.w*v3.z;
                    o3.w += p4.x*v0.w + p4.y*v1.w + p4.z*v2.w + p4.w*v3.w;
                }
            }
        }
    }

    // ---- epilogue: reduce across the 4 row-quarters via reused kt smem ----
    __syncthreads();
    float* xbuf = &kt[0][0];   // 4 sections x [16 q][64 d] = 16 KB (fits in kt)
    {
        const int sec = rq * 1024;
        *(float4*)&xbuf[sec + (qq*4+0)*64 + dcA*4] = o0;
        *(float4*)&xbuf[sec + (qq*4+1)*64 + dcA*4] = o1;
        *(float4*)&xbuf[sec + (qq*4+2)*64 + dcA*4] = o2;
        *(float4*)&xbuf[sec + (qq*4+3)*64 + dcA*4] = o3;
    }
    __syncthreads();

    {
        const int off = pq * 64 + dc * 4;
        float4 a0 = *(const float4*)&xbuf[off];
        float4 a1 = *(const float4*)&xbuf[1024 + off];
        float4 a2 = *(const float4*)&xbuf[2048 + off];
        float4 a3 = *(const float4*)&xbuf[3072 + off];
        float4 r = make_float4(a0.x + a1.x + a2.x + a3.x,
                               a0.y + a1.y + a2.y + a3.y,
                               a0.z + a1.z + a2.z + a3.z,
                               a0.w + a1.w + a2.w + a3.w);
        const size_t pbase = (size_t)blockIdx.x * 1024;
        *(float4*)&g_po[pbase + off] = r;
    }
    if (tid < 16) {
        g_pm[blockIdx.x * 16 + tid] = m_run[tid];
        g_pl[blockIdx.x * 16 + tid] = l_run[tid];
    }
}

// ---------------------------------------------------------------------------
// Combine split partials -> g_obuf [B,S,H*hd]
// ---------------------------------------------------------------------------
__global__ __launch_bounds__(256)
void attn_reduce_kernel() {
    const int bh = blockIdx.x;
    const int tid = threadIdx.x;
    const int pq = tid >> 4, dc = tid & 15;
    const int base = bh * NSPLIT;

    float mm = -1e30f;
    #pragma unroll
    for (int s = 0; s < NSPLIT; s++)
        mm = fmaxf(mm, g_pm[(base + s) * 16 + pq]);

    float4 acc = make_float4(0.f, 0.f, 0.f, 0.f);
    float l = 0.f;
    #pragma unroll
    for (int s = 0; s < NSPLIT; s++) {
        float w = __expf(g_pm[(base + s) * 16 + pq] - mm);
        float4 o = *(const float4*)&g_po[(size_t)(base + s) * 1024 + pq * 64 + dc * 4];
        acc.x += w * o.x; acc.y += w * o.y;
        acc.z += w * o.z; acc.w += w * o.w;
        l += w * g_pl[(base + s) * 16 + pq];
    }
    float inv = 1.0f / l;
    const int b = bh >> 4, h = bh & 15;
    float4 r = make_float4(acc.x * inv, acc.y * inv, acc.z * inv, acc.w * inv);
    *(float4*)&g_obuf[(size_t)(b * 16 + pq) * D_MODEL + h * 64 + dc * 4] = r;
}

// ---------------------------------------------------------------------------
extern "C" void kernel_launch(void* const* d_in, const int* in_sizes, int n_in,
                              void* d_out, int out_size) {
    const float* x       = (const float*)d_in[0];
    const float* cache_k = (const float*)d_in[1];
    const float* cache_v = (const float*)d_in[2];
    const float* qkv_w   = (const float*)d_in[3];
    const float* qkv_b   = (const float*)d_in[4];
    const float* out_w   = (const float*)d_in[5];
    const float* out_b   = (const float*)d_in[6];

    float* out   = (float*)d_out;
    float* out_y = out + OUT_Y_OFF;
    float* out_k = out + OUT_K_OFF;
    float* out_v = out + OUT_V_OFF;

    float *qkv_p = nullptr, *obuf_p = nullptr;
    cudaGetSymbolAddress((void**)&qkv_p,  g_qkv);
    cudaGetSymbolAddress((void**)&obuf_p, g_obuf);

    // 1) QKV projection -> g_qkv [256,3072]
    gemm_bias_kernel<<<dim3(3072 / 64, M_ROWS / 64), 256>>>(
        x, qkv_w, qkv_b, qkv_p, 3072, D_MODEL);

    // 2) Append new K/V rows into out_k/out_v tails
    scatter_newkv_kernel<<<256, 256>>>(out_k, out_v);

    // 3) Fused attention + cache copy-out (split-KV x4)
    attn_split_kernel<<<B_SZ * H_SZ * NSPLIT, 256>>>(cache_k, cache_v, out_k, out_v);

    // 4) Combine splits -> g_obuf
    attn_reduce_kernel<<<B_SZ * H_SZ, 256>>>();

    // 5) Output projection -> y
    gemm_bias_kernel<<<dim3(D_MODEL / 64, M_ROWS / 64), 256>>>(
        obuf_p, out_w, out_b, out_y, D_MODEL, D_MODEL);
}